// round 6
// baseline (speedup 1.0000x reference)
#include <cuda_runtime.h>
#include <math.h>

#define Bsz  4096
#define Tt   512
#define INP  25
#define Hh   50
#define Gg   200
#define KTOT 75
#define KSPL 38          // kh0: k in [0,38), kh1: [38,75)
#define ROWS 32
#define NTH  400         // 50 jj * 4 rg * 2 kh
#define GRID 128         // 128 * 32 = 4096 exactly
#define WS   204         // w_s row stride (floats), permuted gate-interleaved layout
#define XS   32          // xh row stride (floats) -> 128B rows

typedef unsigned long long u64;

__device__ __forceinline__ float sigf(float v) {
    return __fdividef(1.0f, 1.0f + __expf(-v));
}
__device__ __forceinline__ float tanh_fast(float v) {
    return fmaf(2.0f, __fdividef(1.0f, 1.0f + __expf(-2.0f * v)), -1.0f);
}
__device__ __forceinline__ u64 pack2(float lo, float hi) {
    u64 d; asm("mov.b64 %0, {%1, %2};" : "=l"(d) : "f"(lo), "f"(hi)); return d;
}
__device__ __forceinline__ void unpack2(u64 d, float& lo, float& hi) {
    asm("mov.b64 {%0, %1}, %2;" : "=f"(lo), "=f"(hi) : "l"(d));
}
__device__ __forceinline__ u64 fma2(u64 a, u64 b, u64 c) {
    u64 d; asm("fma.rn.f32x2 %0, %1, %2, %3;" : "=l"(d) : "l"(a), "l"(b), "l"(c)); return d;
}
__device__ __forceinline__ u64 add2(u64 a, u64 b) {
    u64 d; asm("add.rn.f32x2 %0, %1, %2;" : "=l"(d) : "l"(a), "l"(b)); return d;
}
__device__ __forceinline__ u64 shfl_xor64(unsigned mask, u64 v, int m) {
    float lo, hi; unpack2(v, lo, hi);
    lo = __shfl_xor_sync(mask, lo, m);
    hi = __shfl_xor_sync(mask, hi, m);
    return pack2(lo, hi);
}

__global__ void __launch_bounds__(NTH, 1)
bayes_lstm_kernel(const float* __restrict__ x,
                  const float* __restrict__ wi_mu, const float* __restrict__ wi_rho,
                  const float* __restrict__ wh_mu, const float* __restrict__ wh_rho,
                  const float* __restrict__ b_mu,  const float* __restrict__ b_rho,
                  const float* __restrict__ lin_w, const float* __restrict__ lin_b,
                  const float* __restrict__ eps_wi, const float* __restrict__ eps_wh,
                  const float* __restrict__ eps_b,
                  float* __restrict__ out)
{
    extern __shared__ float sm[];
    float* w_s  = sm;                    // [75][WS], permuted: w_s[k][jj*4+g] = W[k][g*50+jj]
    float* xhA  = w_s + KTOT * WS;       // [75][XS]  buf 0 (x rows 0..24, h rows 25..74)
    float* xhB  = xhA + KTOT * XS;       // [75][XS]  buf 1

    const int tid  = threadIdx.x;
    const int row0 = blockIdx.x * ROWS;

    // ---- One-time: sample fused weights into gate-interleaved layout ----
    for (int i = tid; i < KTOT * Gg; i += NTH) {
        int k = i / Gg, col = i - k * Gg;          // col = g*50 + jj
        float mu, rho, ep;
        if (k < INP) { mu = wi_mu[i]; rho = wi_rho[i]; ep = eps_wi[i]; }
        else { int i2 = i - INP * Gg; mu = wh_mu[i2]; rho = wh_rho[i2]; ep = eps_wh[i2]; }
        int g = col / Hh, jj = col - g * Hh;
        w_s[k * WS + jj * 4 + g] = fmaf(log1pf(__expf(rho)), ep, mu);
    }
    // zero h rows of buf 0
    for (int i = tid; i < Hh * XS; i += NTH) xhA[INP * XS + i] = 0.0f;
    // x(t=0) into buf 0 (2 elems/thread: 800 = 25*32)
    {
        int r0_ = tid / INP, k0_ = tid - r0_ * INP;
        int t1  = tid + NTH;
        int r1_ = t1 / INP, k1_ = t1 - r1_ * INP;
        xhA[k0_ * XS + r0_] = x[(size_t)(row0 + r0_) * (Tt * INP) + k0_];
        xhA[k1_ * XS + r1_] = x[(size_t)(row0 + r1_) * (Tt * INP) + k1_];
    }

    // ---- Task map ----
    const int p   = tid >> 1;            // pair index 0..199
    const int kh  = tid & 1;
    const int jj  = p % 50;              // h-column
    const int rg  = p / 50;              // 0..3
    const int r0  = rg * 8;
    const int kbeg = kh ? KSPL : 0;
    const int kend = kh ? KTOT : KSPL;
    const unsigned wmask = (tid >= 384) ? 0x0000FFFFu : 0xFFFFFFFFu;

    // bias (injected on kh==0 lanes only; flows through the pair reduction)
    u64 bias2[4];
    #pragma unroll
    for (int g = 0; g < 4; g++) {
        float b = 0.0f;
        if (kh == 0) {
            int j = g * Hh + jj;
            b = fmaf(log1pf(__expf(b_rho[j])), eps_b[j], b_mu[j]);
        }
        bias2[g] = pack2(b, b);
    }

    // x prefetch bases (2 elems/thread)
    const int pr0 = tid / INP,        pk0 = tid - pr0 * INP;
    const int pr1 = (tid + NTH) / INP, pk1 = (tid + NTH) - pr1 * INP;
    const size_t xb0 = (size_t)(row0 + pr0) * (Tt * INP) + pk0;
    const size_t xb1 = (size_t)(row0 + pr1) * (Tt * INP) + pk1;

    // cell state in registers: rows r0+4*kh .. +3
    float c_reg[4] = {0.f, 0.f, 0.f, 0.f};

    const float* wp = w_s + jj * 4;
    __syncthreads();

    for (int t = 0; t < Tt; ++t) {
        const float* cur = (t & 1) ? xhB : xhA;
        float*       nxt = (t & 1) ? xhA : xhB;

        float px0 = 0.f, px1 = 0.f;
        if (t + 1 < Tt) {
            px0 = x[xb0 + (size_t)(t + 1) * INP];
            px1 = x[xb1 + (size_t)(t + 1) * INP];
        }

        // ---- Gate GEMM: acc[g][vp], vp = r-pair (r0+2vp, r0+2vp+1), packed f32x2 ----
        u64 a0[4], a1[4], a2[4], a3[4];   // per gate g: a_g[vp]
        #pragma unroll
        for (int vp = 0; vp < 4; vp++) { a0[vp] = bias2[0]; a1[vp] = bias2[1];
                                         a2[vp] = bias2[2]; a3[vp] = bias2[3]; }

        const float* vrow = cur + r0;
        #pragma unroll 4
        for (int k = kbeg; k < kend; ++k) {
            float4 w4 = *(const float4*)(wp + k * WS);          // (i,f,g,o) for column jj
            float4 hA = *(const float4*)(vrow + k * XS);        // rows r0..r0+3
            float4 hB = *(const float4*)(vrow + k * XS + 4);    // rows r0+4..r0+7
            u64 hp0 = pack2(hA.x, hA.y);
            u64 hp1 = pack2(hA.z, hA.w);
            u64 hp2 = pack2(hB.x, hB.y);
            u64 hp3 = pack2(hB.z, hB.w);
            u64 wd;
            wd = pack2(w4.x, w4.x);
            a0[0] = fma2(wd, hp0, a0[0]); a0[1] = fma2(wd, hp1, a0[1]);
            a0[2] = fma2(wd, hp2, a0[2]); a0[3] = fma2(wd, hp3, a0[3]);
            wd = pack2(w4.y, w4.y);
            a1[0] = fma2(wd, hp0, a1[0]); a1[1] = fma2(wd, hp1, a1[1]);
            a1[2] = fma2(wd, hp2, a1[2]); a1[3] = fma2(wd, hp3, a1[3]);
            wd = pack2(w4.z, w4.z);
            a2[0] = fma2(wd, hp0, a2[0]); a2[1] = fma2(wd, hp1, a2[1]);
            a2[2] = fma2(wd, hp2, a2[2]); a2[3] = fma2(wd, hp3, a2[3]);
            wd = pack2(w4.w, w4.w);
            a3[0] = fma2(wd, hp0, a3[0]); a3[1] = fma2(wd, hp1, a3[1]);
            a3[2] = fma2(wd, hp2, a3[2]); a3[3] = fma2(wd, hp3, a3[3]);
        }

        // ---- Pair split-K reduction: kh0 keeps vp 0,1 ; kh1 keeps vp 2,3 ----
        #pragma unroll
        for (int vp = 0; vp < 2; vp++) {
            u64 got;
            got = shfl_xor64(wmask, kh ? a0[vp] : a0[vp + 2], 1);
            if (kh == 0) a0[vp] = add2(a0[vp], got); else a0[vp + 2] = add2(a0[vp + 2], got);
            got = shfl_xor64(wmask, kh ? a1[vp] : a1[vp + 2], 1);
            if (kh == 0) a1[vp] = add2(a1[vp], got); else a1[vp + 2] = add2(a1[vp + 2], got);
            got = shfl_xor64(wmask, kh ? a2[vp] : a2[vp + 2], 1);
            if (kh == 0) a2[vp] = add2(a2[vp], got); else a2[vp + 2] = add2(a2[vp + 2], got);
            got = shfl_xor64(wmask, kh ? a3[vp] : a3[vp + 2], 1);
            if (kh == 0) a3[vp] = add2(a3[vp], got); else a3[vp + 2] = add2(a3[vp + 2], got);
        }

        // ---- In-register epilogue on owned 4 rows ----
        {
            const int o0 = kh ? 2 : 0;
            float gi[4], gf[4], gg[4], go[4];
            unpack2(a0[o0], gi[0], gi[1]); unpack2(a0[o0 + 1], gi[2], gi[3]);
            unpack2(a1[o0], gf[0], gf[1]); unpack2(a1[o0 + 1], gf[2], gf[3]);
            unpack2(a2[o0], gg[0], gg[1]); unpack2(a2[o0 + 1], gg[2], gg[3]);
            unpack2(a3[o0], go[0], go[1]); unpack2(a3[o0 + 1], go[2], go[3]);
            float hv[4];
            #pragma unroll
            for (int e = 0; e < 4; e++) {
                float c = fmaf(sigf(gf[e]), c_reg[e], sigf(gi[e]) * tanh_fast(gg[e]));
                c_reg[e] = c;
                hv[e] = sigf(go[e]) * tanh_fast(c);
            }
            *(float4*)(nxt + (INP + jj) * XS + r0 + 4 * kh) =
                make_float4(hv[0], hv[1], hv[2], hv[3]);
        }

        // commit prefetched x(t+1) into nxt x-rows
        if (t + 1 < Tt) {
            nxt[pk0 * XS + pr0] = px0;
            nxt[pk1 * XS + pr1] = px1;
        }
        __syncthreads();   // one barrier per step
    }

    // ---- Head: final h is in xhA (t=511 wrote nxt=xhA) ----
    if (tid < ROWS) {
        float s = lin_b[0];
        #pragma unroll
        for (int m = 0; m < Hh; m++)
            s = fmaf(xhA[(INP + m) * XS + tid], lin_w[m], s);
        out[row0 + tid] = s;
    }
}

extern "C" void kernel_launch(void* const* d_in, const int* in_sizes, int n_in,
                              void* d_out, int out_size)
{
    const size_t smem_bytes =
        (size_t)(KTOT * WS + 2 * KTOT * XS) * sizeof(float);   // 15300 + 4800 floats = 80400 B
    cudaFuncSetAttribute(bayes_lstm_kernel,
                         cudaFuncAttributeMaxDynamicSharedMemorySize,
                         (int)smem_bytes);
    bayes_lstm_kernel<<<GRID, NTH, smem_bytes>>>(
        (const float*)d_in[0],  (const float*)d_in[1],  (const float*)d_in[2],
        (const float*)d_in[3],  (const float*)d_in[4],  (const float*)d_in[5],
        (const float*)d_in[6],  (const float*)d_in[7],  (const float*)d_in[8],
        (const float*)d_in[9],  (const float*)d_in[10], (const float*)d_in[11],
        (float*)d_out);
}

// round 7
// speedup vs baseline: 1.5699x; 1.5699x over previous
#include <cuda_runtime.h>
#include <math.h>

#define Bsz  4096
#define Tt   512
#define INP  25
#define Hh   50
#define Gg   200
#define KTOT 75
#define KSPL 37          // kh0: k in [0,37), kh1: [37,75)
#define ROWS 28
#define NTH  704         // 22 warps
#define GRID 147

typedef unsigned long long u64;

__device__ __forceinline__ float sigf(float v) {
    return __fdividef(1.0f, 1.0f + __expf(-v));
}
__device__ __forceinline__ float tanh_fast(float v) {
    return fmaf(2.0f, __fdividef(1.0f, 1.0f + __expf(-2.0f * v)), -1.0f);
}
__device__ __forceinline__ u64 pack2(float lo, float hi) {
    u64 d; asm("mov.b64 %0, {%1, %2};" : "=l"(d) : "f"(lo), "f"(hi)); return d;
}
__device__ __forceinline__ void unpack2(u64 d, float& lo, float& hi) {
    asm("mov.b64 {%0, %1}, %2;" : "=f"(lo), "=f"(hi) : "l"(d));
}
__device__ __forceinline__ u64 fma2(u64 a, u64 b, u64 c) {
    u64 d; asm("fma.rn.f32x2 %0, %1, %2, %3;" : "=l"(d) : "l"(a), "l"(b), "l"(c)); return d;
}
__device__ __forceinline__ u64 add2(u64 a, u64 b) {
    u64 d; asm("add.rn.f32x2 %0, %1, %2;" : "=l"(d) : "l"(a), "l"(b)); return d;
}
__device__ __forceinline__ u64 shfl_xor64(u64 v, int m) {
    float lo, hi; unpack2(v, lo, hi);
    lo = __shfl_xor_sync(0xffffffffu, lo, m);
    hi = __shfl_xor_sync(0xffffffffu, hi, m);
    return pack2(lo, hi);
}

__global__ void __launch_bounds__(NTH, 1)
bayes_lstm_kernel(const float* __restrict__ x,
                  const float* __restrict__ wi_mu, const float* __restrict__ wi_rho,
                  const float* __restrict__ wh_mu, const float* __restrict__ wh_rho,
                  const float* __restrict__ b_mu,  const float* __restrict__ b_rho,
                  const float* __restrict__ lin_w, const float* __restrict__ lin_b,
                  const float* __restrict__ eps_wi, const float* __restrict__ eps_wh,
                  const float* __restrict__ eps_b,
                  float* __restrict__ out)
{
    extern __shared__ float sm[];
    float* w_s = sm;                     // [75][Gg] gate-interleaved: w_s[k][jj*4+g] = W[k][g*50+jj]
    float* xhA = w_s + KTOT * Gg;        // [75][ROWS] buf 0 (x rows 0..24, h rows 25..74)
    float* xhB = xhA + KTOT * ROWS;      // [75][ROWS] buf 1

    const int tid  = threadIdx.x;
    const long row0 = (long)blockIdx.x * ROWS;

    // ---- One-time: sample fused weights into gate-interleaved layout ----
    for (int i = tid; i < KTOT * Gg; i += NTH) {
        int k = i / Gg, col = i - k * Gg;          // col = g*50 + jj
        float mu, rho, ep;
        if (k < INP) { mu = wi_mu[i]; rho = wi_rho[i]; ep = eps_wi[i]; }
        else { int i2 = i - INP * Gg; mu = wh_mu[i2]; rho = wh_rho[i2]; ep = eps_wh[i2]; }
        int g = col / Hh, jj = col - g * Hh;
        w_s[k * Gg + jj * 4 + g] = fmaf(log1pf(__expf(rho)), ep, mu);
    }
    // zero h rows of buf 0
    for (int i = tid; i < Hh * ROWS; i += NTH) xhA[INP * ROWS + i] = 0.0f;
    // x(t=0) into buf 0 (700 elems; one per thread, tid<700)
    {
        const int r = tid / INP, k = tid % INP;
        if (tid < INP * ROWS) {
            float v = 0.0f;
            if (row0 + r < Bsz) v = x[(size_t)(row0 + r) * (Tt * INP) + k];
            xhA[k * ROWS + r] = v;
        }
    }

    // ---- Task map: pair of lane-adjacent threads per (jj, 4-row) tile ----
    const bool act  = (tid < 700);
    const int  tile = act ? (tid >> 1) : 349;
    const int  kh   = tid & 1;
    const int  jj   = tile % 50;         // h-column
    const int  rr0  = (tile / 50) * 4;   // rows rr0..rr0+3
    const int  kbeg = kh ? KSPL : 0;
    const int  kend = kh ? KTOT : KSPL;

    // bias (kh==0 lanes only; flows through the bidirectional pair reduction)
    u64 bias2[4];
    #pragma unroll
    for (int g = 0; g < 4; g++) {
        float b = 0.0f;
        if (kh == 0) {
            int j = g * Hh + jj;
            b = fmaf(log1pf(__expf(b_rho[j])), eps_b[j], b_mu[j]);
        }
        bias2[g] = pack2(b, b);
    }

    // x prefetch map (1 elem/thread)
    const int  pr = tid / INP, pk = tid % INP;
    const bool pf_ok = (tid < INP * ROWS) && (row0 + pr < Bsz);
    const size_t pf_base = pf_ok ? ((size_t)(row0 + pr) * (Tt * INP) + pk) : 0;

    // cell state in registers: this lane owns rows rr0+2*kh, rr0+2*kh+1
    float c0 = 0.0f, c1 = 0.0f;

    const float* wp = w_s + jj * 4;
    __syncthreads();

    for (int t = 0; t < Tt; ++t) {
        const float* cur = (t & 1) ? xhB : xhA;
        float*       nxt = (t & 1) ? xhA : xhB;

        float pf = 0.0f;
        if (pf_ok && t + 1 < Tt) pf = x[pf_base + (size_t)(t + 1) * INP];

        // ---- Gate GEMM: a[g][vp], vp=0 -> rows (rr0,rr0+1), vp=1 -> (rr0+2,rr0+3) ----
        u64 a0[2], a1[2], a2[2], a3[2];
        a0[0] = bias2[0]; a0[1] = bias2[0];
        a1[0] = bias2[1]; a1[1] = bias2[1];
        a2[0] = bias2[2]; a2[1] = bias2[2];
        a3[0] = bias2[3]; a3[1] = bias2[3];

        const float* vrow = cur + rr0;
        #pragma unroll 4
        for (int k = kbeg; k < kend; ++k) {
            float4 w4 = *(const float4*)(wp + k * Gg);      // (i,f,g,o) of column jj
            float4 hv = *(const float4*)(vrow + k * ROWS);  // rows rr0..rr0+3
            u64 h01 = pack2(hv.x, hv.y);
            u64 h23 = pack2(hv.z, hv.w);
            u64 wd;
            wd = pack2(w4.x, w4.x); a0[0] = fma2(wd, h01, a0[0]); a0[1] = fma2(wd, h23, a0[1]);
            wd = pack2(w4.y, w4.y); a1[0] = fma2(wd, h01, a1[0]); a1[1] = fma2(wd, h23, a1[1]);
            wd = pack2(w4.z, w4.z); a2[0] = fma2(wd, h01, a2[0]); a2[1] = fma2(wd, h23, a2[1]);
            wd = pack2(w4.w, w4.w); a3[0] = fma2(wd, h01, a3[0]); a3[1] = fma2(wd, h23, a3[1]);
        }

        // ---- Bidirectional pair reduction: both lanes get full sums ----
        #pragma unroll
        for (int vp = 0; vp < 2; vp++) {
            a0[vp] = add2(a0[vp], shfl_xor64(a0[vp], 1));
            a1[vp] = add2(a1[vp], shfl_xor64(a1[vp], 1));
            a2[vp] = add2(a2[vp], shfl_xor64(a2[vp], 1));
            a3[vp] = add2(a3[vp], shfl_xor64(a3[vp], 1));
        }

        // ---- In-register epilogue: this lane's 2 rows (vp = kh) ----
        {
            float gi0, gi1, gf0, gf1, gg0, gg1, go0, go1;
            unpack2(a0[kh], gi0, gi1);
            unpack2(a1[kh], gf0, gf1);
            unpack2(a2[kh], gg0, gg1);
            unpack2(a3[kh], go0, go1);
            float cn0 = fmaf(sigf(gf0), c0, sigf(gi0) * tanh_fast(gg0));
            float cn1 = fmaf(sigf(gf1), c1, sigf(gi1) * tanh_fast(gg1));
            c0 = cn0; c1 = cn1;
            float h0 = sigf(go0) * tanh_fast(cn0);
            float h1 = sigf(go1) * tanh_fast(cn1);
            if (act)
                *(float2*)(nxt + (INP + jj) * ROWS + rr0 + 2 * kh) = make_float2(h0, h1);
        }

        // commit prefetched x(t+1) into nxt x-rows
        if (pf_ok && t + 1 < Tt) nxt[pk * ROWS + pr] = pf;

        __syncthreads();   // one barrier per step: nxt fully built
    }

    // ---- Head: t=511 (odd) wrote nxt = xhA ----
    if (tid < ROWS && row0 + tid < Bsz) {
        float s = lin_b[0];
        #pragma unroll
        for (int m = 0; m < Hh; m++)
            s = fmaf(xhA[(INP + m) * ROWS + tid], lin_w[m], s);
        out[row0 + tid] = s;
    }
}

extern "C" void kernel_launch(void* const* d_in, const int* in_sizes, int n_in,
                              void* d_out, int out_size)
{
    const size_t smem_bytes =
        (size_t)(KTOT * Gg + 2 * KTOT * ROWS) * sizeof(float);   // 15000 + 4200 floats = 76800 B
    cudaFuncSetAttribute(bayes_lstm_kernel,
                         cudaFuncAttributeMaxDynamicSharedMemorySize,
                         (int)smem_bytes);
    bayes_lstm_kernel<<<GRID, NTH, smem_bytes>>>(
        (const float*)d_in[0],  (const float*)d_in[1],  (const float*)d_in[2],
        (const float*)d_in[3],  (const float*)d_in[4],  (const float*)d_in[5],
        (const float*)d_in[6],  (const float*)d_in[7],  (const float*)d_in[8],
        (const float*)d_in[9],  (const float*)d_in[10], (const float*)d_in[11],
        (float*)d_out);
}